// round 1
// baseline (speedup 1.0000x reference)
#include <cuda_runtime.h>
#include <math.h>

// Problem constants
#define K_TOT 8192      // N_T * BS rows
#define D     128
#define BSZ   2048
#define NT    4
#define INV_TEMP 2.0f   // 1 / 0.5
#define KPOS  24576.0f  // N*(N-1)*BS

// Tiling
#define TI 64           // rows per block
#define TJ 128          // cols per tile
#define NBLK (K_TOT / TI)   // 128
#define NTILE (K_TOT / TJ)  // 64

// Scratch (device globals; allocation-free rule)
__device__ float g_sn[K_TOT * D];
__device__ float g_partial[NBLK];

// ---------------------------------------------------------------------------
// Kernel 1: row L2-normalize. One warp per row, float4 lanes.
// ---------------------------------------------------------------------------
__global__ void normalize_kernel(const float* __restrict__ z) {
    int gwarp = (blockIdx.x * blockDim.x + threadIdx.x) >> 5;
    int lane = threadIdx.x & 31;
    if (gwarp >= K_TOT) return;
    float4 v = ((const float4*)(z + gwarp * D))[lane];
    float ss = v.x * v.x + v.y * v.y + v.z * v.z + v.w * v.w;
    #pragma unroll
    for (int off = 16; off; off >>= 1)
        ss += __shfl_xor_sync(0xffffffffu, ss, off);
    float inv = 1.0f / fmaxf(sqrtf(ss), 1e-8f);
    float4 o = make_float4(v.x * inv, v.y * inv, v.z * inv, v.w * inv);
    ((float4*)(g_sn + gwarp * D))[lane] = o;
}

// ---------------------------------------------------------------------------
// Kernel 2: fused simmat + online softmax over negatives + positives capture.
// Block: 256 threads = 8 warps. ty = warp (owns 8 rows), tx = lane (owns 4 cols
// of each 128-col tile). Smem holds transposed [k][j] tiles so the inner loop
// is: 1x LDS.128 B (contiguous across lanes) + 2x LDS.128 A (broadcast).
// ---------------------------------------------------------------------------
#define SB_STRIDE 132   // 128 + 4 pad, keeps 16B alignment (132*4 = 33*16)
#define SA_STRIDE 68    // 64 + 4 pad  (68*4 = 17*16)
#define SB_ELEMS (D * SB_STRIDE)          // 16896 floats
#define SA_ELEMS (D * SA_STRIDE)          // 8704 floats
#define POS_OFF  (SB_ELEMS + SA_ELEMS)
#define SMEM_FLOATS (POS_OFF + TI * NT)
#define SMEM_BYTES (SMEM_FLOATS * sizeof(float))

__global__ void __launch_bounds__(256) clblock_main_kernel() {
    extern __shared__ float smem[];
    float* sB = smem;                       // [D][SB_STRIDE]  (sB[k][j] = sn[c0+j][k])
    float* sA = smem + SB_ELEMS;            // [D][SA_STRIDE]  (sA[k][r] = sn[base+r][k])
    float* sPos = smem + POS_OFF;           // [TI][NT]
    __shared__ float wsum[8];

    const int t  = threadIdx.x;
    const int tx = t & 31;
    const int ty = t >> 5;
    const int base = blockIdx.x * TI;

    // Load A tile once (rows fixed for this block), transposed.
    #pragma unroll
    for (int it = 0; it < 8; ++it) {
        int idx = t + 256 * it;             // 0..2047 -> (rg, k)
        int rg = idx >> 7;                  // 0..15 (groups of 4 rows)
        int k  = idx & 127;
        float4 v;
        v.x = g_sn[(base + rg * 4 + 0) * D + k];
        v.y = g_sn[(base + rg * 4 + 1) * D + k];
        v.z = g_sn[(base + rg * 4 + 2) * D + k];
        v.w = g_sn[(base + rg * 4 + 3) * D + k];
        *(float4*)&sA[k * SA_STRIDE + rg * 4] = v;
    }

    float m[8], S[8];
    #pragma unroll
    for (int r = 0; r < 8; ++r) { m[r] = -INFINITY; S[r] = 0.0f; }

    for (int tile = 0; tile < NTILE; ++tile) {
        const int c0 = tile * TJ;
        __syncthreads();   // prior tile's reads of sB are done
        // Fill B tile transposed.
        #pragma unroll
        for (int it = 0; it < 16; ++it) {
            int idx = t + 256 * it;         // 0..4095 -> (jg, k)
            int jg = idx >> 7;              // 0..31
            int k  = idx & 127;
            float4 v;
            v.x = g_sn[(c0 + jg * 4 + 0) * D + k];
            v.y = g_sn[(c0 + jg * 4 + 1) * D + k];
            v.z = g_sn[(c0 + jg * 4 + 2) * D + k];
            v.w = g_sn[(c0 + jg * 4 + 3) * D + k];
            *(float4*)&sB[k * SB_STRIDE + jg * 4] = v;
        }
        __syncthreads();

        // 8x4 micro-tile GEMM over full K=128.
        float acc[8][4];
        #pragma unroll
        for (int r = 0; r < 8; ++r)
            #pragma unroll
            for (int c = 0; c < 4; ++c) acc[r][c] = 0.0f;

        #pragma unroll 8
        for (int k = 0; k < D; ++k) {
            float4 b  = *(const float4*)&sB[k * SB_STRIDE + tx * 4];
            float4 a0 = *(const float4*)&sA[k * SA_STRIDE + ty * 8];
            float4 a1 = *(const float4*)&sA[k * SA_STRIDE + ty * 8 + 4];
            float a[8] = {a0.x, a0.y, a0.z, a0.w, a1.x, a1.y, a1.z, a1.w};
            float bb[4] = {b.x, b.y, b.z, b.w};
            #pragma unroll
            for (int r = 0; r < 8; ++r)
                #pragma unroll
                for (int c = 0; c < 4; ++c)
                    acc[r][c] += a[r] * bb[c];
        }

        // Online softmax epilogue with exclusion mask; capture positives.
        #pragma unroll
        for (int r = 0; r < 8; ++r) {
            const int i = base + ty * 8 + r;
            float sim[4];
            bool val[4];
            float tmax = -INFINITY;
            #pragma unroll
            for (int c = 0; c < 4; ++c) {
                int j = c0 + tx * 4 + c;
                sim[c] = acc[r][c] * INV_TEMP;
                val[c] = ((j ^ i) & (BSZ - 1)) != 0;
                if (val[c]) {
                    tmax = fmaxf(tmax, sim[c]);
                } else if (j != i) {
                    sPos[(ty * 8 + r) * NT + (j >> 11)] = sim[c];
                }
            }
            float nm = fmaxf(m[r], tmax);
            float s  = S[r] * __expf(m[r] - nm);
            #pragma unroll
            for (int c = 0; c < 4; ++c)
                if (val[c]) s += __expf(sim[c] - nm);
            m[r] = nm; S[r] = s;
        }
    }

    // Merge (m,S) across the 32 column-owner lanes of each warp, then compute
    // the per-row loss contribution on lane 0 (positives were written by lanes
    // of THIS warp -> __syncwarp is sufficient).
    __syncwarp();
    float contrib = 0.0f;
    #pragma unroll
    for (int r = 0; r < 8; ++r) {
        float mw = m[r];
        #pragma unroll
        for (int off = 16; off; off >>= 1)
            mw = fmaxf(mw, __shfl_xor_sync(0xffffffffu, mw, off));
        float Sv = S[r] * __expf(m[r] - mw);
        #pragma unroll
        for (int off = 16; off; off >>= 1)
            Sv += __shfl_xor_sync(0xffffffffu, Sv, off);
        if (tx == 0) {
            int i = base + ty * 8 + r;
            int q = i >> 11;
            #pragma unroll
            for (int qq = 0; qq < NT; ++qq) {
                if (qq == q) continue;
                float pos = sPos[(ty * 8 + r) * NT + qq];
                float mm  = fmaxf(pos, mw);
                float lse = mm + logf(__expf(pos - mm) + Sv * __expf(mw - mm));
                contrib += lse - pos;
            }
        }
    }
    if (tx == 0) wsum[ty] = contrib;
    __syncthreads();
    if (t == 0) {
        float s = 0.0f;
        #pragma unroll
        for (int w = 0; w < 8; ++w) s += wsum[w];
        g_partial[blockIdx.x] = s;
    }
}

// ---------------------------------------------------------------------------
// Kernel 3: deterministic final reduction of 128 block partials.
// ---------------------------------------------------------------------------
__global__ void final_kernel(float* __restrict__ out) {
    __shared__ float sh[4];
    int t = threadIdx.x;
    float v = g_partial[t];
    #pragma unroll
    for (int off = 16; off; off >>= 1)
        v += __shfl_xor_sync(0xffffffffu, v, off);
    if ((t & 31) == 0) sh[t >> 5] = v;
    __syncthreads();
    if (t == 0) out[0] = (sh[0] + sh[1] + sh[2] + sh[3]) / KPOS;
}

// ---------------------------------------------------------------------------
extern "C" void kernel_launch(void* const* d_in, const int* in_sizes, int n_in,
                              void* d_out, int out_size) {
    const float* z = (const float*)d_in[0];
    float* out = (float*)d_out;

    cudaFuncSetAttribute(clblock_main_kernel,
                         cudaFuncAttributeMaxDynamicSharedMemorySize,
                         (int)SMEM_BYTES);

    normalize_kernel<<<K_TOT / 8, 256>>>(z);
    clblock_main_kernel<<<NBLK, 256, SMEM_BYTES>>>();
    final_kernel<<<1, 128>>>(out);
}

// round 3
// speedup vs baseline: 4.9492x; 4.9492x over previous
#include <cuda_runtime.h>
#include <cuda_bf16.h>
#include <cstdint>
#include <math.h>

// ---------------------------------------------------------------------------
// Problem constants
// ---------------------------------------------------------------------------
#define K_TOT 8192      // N_T * BS rows
#define D     128
#define NBLK  128       // grid of main kernel (64 rows each)
#define NCHUNK 64       // 8192 / 128 column chunks
#define KPOS  24576.0f  // N*(N-1)*BS
#define SCALE_F 1.69864368f   // sqrt(2 * log2(e));  acc = log2e * sim
#define LN2F   0.693147181f

// Smem layout (bytes)
#define SM_B0   0
#define SM_B1   32768
#define SM_A    65536          // 64 rows x 256B
#define SM_POS  81920          // 64 x 4 floats
#define SM_SS   82944          // 64 x 2 floats
#define SM_RED  83456          // 4 floats
#define SM_TOTAL 83472

// Scratch
__device__ __align__(16) __nv_bfloat16 g_snb[K_TOT * D];
__device__ float g_partial[NBLK];

// ---------------------------------------------------------------------------
// PTX helpers
// ---------------------------------------------------------------------------
__device__ __forceinline__ float ex2f(float x) {
    float r; asm("ex2.approx.f32 %0, %1;" : "=f"(r) : "f"(x)); return r;
}

#define CP16(dst, src) \
    asm volatile("cp.async.cg.shared.global [%0], [%1], 16;\n" :: "r"(dst), "l"(src))
#define CPCOMMIT() asm volatile("cp.async.commit_group;\n")
#define CPWAIT1()  asm volatile("cp.async.wait_group 1;\n")
#define CPWAIT0()  asm volatile("cp.async.wait_group 0;\n")

#define LDSM4(R0,R1,R2,R3,ADDR) \
    asm volatile("ldmatrix.sync.aligned.m8n8.x4.shared.b16 {%0,%1,%2,%3}, [%4];\n" \
        : "=r"(R0),"=r"(R1),"=r"(R2),"=r"(R3) : "r"(ADDR))

#define MMA16816(D0,D1,D2,D3,A0,A1,A2,A3,B0,B1) \
    asm volatile("mma.sync.aligned.m16n8k16.row.col.f32.bf16.bf16.f32 " \
        "{%0,%1,%2,%3}, {%4,%5,%6,%7}, {%8,%9}, {%0,%1,%2,%3};\n" \
        : "+f"(D0),"+f"(D1),"+f"(D2),"+f"(D3) \
        : "r"(A0),"r"(A1),"r"(A2),"r"(A3),"r"(B0),"r"(B1))

// ---------------------------------------------------------------------------
// Kernel 1: row L2-normalize, pre-scale by sqrt(2*log2e), emit bf16.
// One warp per row.
// ---------------------------------------------------------------------------
__global__ void normalize_kernel(const float* __restrict__ z) {
    int gw = (blockIdx.x * blockDim.x + threadIdx.x) >> 5;
    int lane = threadIdx.x & 31;
    float4 v = ((const float4*)(z + (size_t)gw * D))[lane];
    float ss = v.x*v.x + v.y*v.y + v.z*v.z + v.w*v.w;
    #pragma unroll
    for (int off = 16; off; off >>= 1)
        ss += __shfl_xor_sync(0xffffffffu, ss, off);
    float inv = SCALE_F / fmaxf(sqrtf(ss), 1e-8f);
    __nv_bfloat162 p0 = __floats2bfloat162_rn(v.x * inv, v.y * inv);
    __nv_bfloat162 p1 = __floats2bfloat162_rn(v.z * inv, v.w * inv);
    uint2 o;
    o.x = *(unsigned int*)&p0;
    o.y = *(unsigned int*)&p1;
    *(uint2*)(g_snb + (size_t)gw * D + lane * 4) = o;
}

// ---------------------------------------------------------------------------
// B chunk loader: 128 cols x 128 k bf16 (32KB) with 16B-chunk XOR swizzle.
// ---------------------------------------------------------------------------
__device__ __forceinline__ void load_B(uint32_t sb, int buf, int chunk, int t) {
    const char* gB = (const char*)g_snb + (size_t)chunk * 128 * 256;
    uint32_t base = sb + (buf ? SM_B1 : SM_B0);
    #pragma unroll
    for (int it = 0; it < 16; ++it) {
        int f = t + 128 * it;          // 0..2047
        int j = f >> 4, c = f & 15;
        uint32_t dst = base + j * 256 + ((c ^ (j & 7)) << 4);
        CP16(dst, gB + j * 256 + c * 16);
    }
}

// ---------------------------------------------------------------------------
// Kernel 2: HMMA simmat + fixed-offset softmax accumulation + positives.
// 128 blocks x 128 threads. Block = 64 rows; warps are 2x2:
//   wr = w>>1 (row half: 32 rows), wc = w&1 (col half: 64 of 128 chunk cols).
// A fragments register-resident for the whole kernel.
// ---------------------------------------------------------------------------
__global__ void __launch_bounds__(128) clblock_mma_kernel() {
    extern __shared__ char smem[];
    float* sPos = (float*)(smem + SM_POS);   // [64][4]
    float* sS   = (float*)(smem + SM_SS);    // [64][2]
    float* sRed = (float*)(smem + SM_RED);   // [4]

    const int t = threadIdx.x, lane = t & 31, w = t >> 5;
    const int wr = w >> 1, wc = w & 1;
    const int rb = blockIdx.x * 64;
    const int rwb = rb + wr * 32;
    uint32_t sb = (uint32_t)__cvta_generic_to_shared(smem);

    // ---- async load A tile (64x128 bf16) + B chunks 0,1 ----
    {
        const char* gA = (const char*)(g_snb + (size_t)rb * D);
        #pragma unroll
        for (int it = 0; it < 8; ++it) {
            int f = t + 128 * it;      // 0..1023
            int r = f >> 4, c = f & 15;
            CP16(sb + SM_A + r * 256 + ((c ^ (r & 7)) << 4), gA + r * 256 + c * 16);
        }
        load_B(sb, 0, 0, t);
    }
    CPCOMMIT();
    load_B(sb, 1, 1, t);
    CPCOMMIT();
    CPWAIT1();              // group0 (A + chunk0) complete
    __syncthreads();

    // ---- A fragments: 2 m-tiles x 8 k-steps x 4 regs, resident ----
    uint32_t af[2][8][4];
    #pragma unroll
    for (int mt = 0; mt < 2; ++mt) {
        int row = wr * 32 + mt * 16 + (lane & 15);
        uint32_t rbase = sb + SM_A + row * 256;
        #pragma unroll
        for (int ks = 0; ks < 8; ++ks) {
            uint32_t addr = rbase + (((ks * 2 + (lane >> 4)) ^ (row & 7)) << 4);
            LDSM4(af[mt][ks][0], af[mt][ks][1], af[mt][ks][2], af[mt][ks][3], addr);
        }
    }

    float Ssum[4] = {0.f, 0.f, 0.f, 0.f};

    for (int ch = 0; ch < NCHUNK; ++ch) {
        const int cb = ch * 128;
        uint32_t Bb = sb + ((ch & 1) ? SM_B1 : SM_B0);

        float acc[2][8][4];
        #pragma unroll
        for (int mt = 0; mt < 2; ++mt)
            #pragma unroll
            for (int nt = 0; nt < 8; ++nt)
                #pragma unroll
                for (int e = 0; e < 4; ++e) acc[mt][nt][e] = 0.f;

        #pragma unroll
        for (int ks = 0; ks < 8; ++ks) {
            #pragma unroll
            for (int ntp = 0; ntp < 4; ++ntp) {
                int colr = wc * 64 + ntp * 16 + (lane & 15);
                uint32_t addr = Bb + colr * 256 +
                                (((ks * 2 + (lane >> 4)) ^ (colr & 7)) << 4);
                uint32_t b0, b1, b2, b3;
                LDSM4(b0, b1, b2, b3, addr);
                MMA16816(acc[0][2*ntp][0], acc[0][2*ntp][1], acc[0][2*ntp][2], acc[0][2*ntp][3],
                         af[0][ks][0], af[0][ks][1], af[0][ks][2], af[0][ks][3], b0, b2);
                MMA16816(acc[1][2*ntp][0], acc[1][2*ntp][1], acc[1][2*ntp][2], acc[1][2*ntp][3],
                         af[1][ks][0], af[1][ks][1], af[1][ks][2], af[1][ks][3], b0, b2);
                MMA16816(acc[0][2*ntp+1][0], acc[0][2*ntp+1][1], acc[0][2*ntp+1][2], acc[0][2*ntp+1][3],
                         af[0][ks][0], af[0][ks][1], af[0][ks][2], af[0][ks][3], b1, b3);
                MMA16816(acc[1][2*ntp+1][0], acc[1][2*ntp+1][1], acc[1][2*ntp+1][2], acc[1][2*ntp+1][3],
                         af[1][ks][0], af[1][ks][1], af[1][ks][2], af[1][ks][3], b1, b3);
            }
        }

        // Collision columns (j == i mod 2048) hit this warp only when the
        // 128-aligned window and 64-half match.
        bool special = (((rwb ^ cb) & 0x780) == 0) && (((rwb >> 6) & 1) == wc);
        if (!special) {
            #pragma unroll
            for (int mt = 0; mt < 2; ++mt)
                #pragma unroll
                for (int nt = 0; nt < 8; ++nt) {
                    Ssum[mt*2+0] += ex2f(acc[mt][nt][0]) + ex2f(acc[mt][nt][1]);
                    Ssum[mt*2+1] += ex2f(acc[mt][nt][2]) + ex2f(acc[mt][nt][3]);
                }
        } else {
            #pragma unroll
            for (int mt = 0; mt < 2; ++mt)
                #pragma unroll
                for (int nt = 0; nt < 8; ++nt)
                    #pragma unroll
                    for (int e = 0; e < 4; ++e) {
                        int i = rwb + mt * 16 + (lane >> 2) + ((e >> 1) << 3);
                        int j = cb + wc * 64 + nt * 8 + ((lane & 3) << 1) + (e & 1);
                        float v = acc[mt][nt][e];
                        if (((i ^ j) & 2047) == 0) {
                            if (i != j) sPos[(i - rb) * 4 + (j >> 11)] = v;
                        } else {
                            Ssum[mt*2 + (e >> 1)] += ex2f(v);
                        }
                    }
        }

        __syncthreads();                        // everyone done reading B[ch&1]
        if (ch + 2 < NCHUNK) {
            load_B(sb, ch & 1, ch + 2, t);
            CPCOMMIT();
            CPWAIT1();                          // chunk ch+1 ready
        } else if (ch + 1 < NCHUNK) {
            CPWAIT0();                          // last chunk ready
        }
        __syncthreads();
    }

    // ---- per-row S0: reduce across the 4 lanes of each quad, then halves ----
    #pragma unroll
    for (int s = 0; s < 4; ++s) {
        Ssum[s] += __shfl_xor_sync(0xffffffffu, Ssum[s], 1);
        Ssum[s] += __shfl_xor_sync(0xffffffffu, Ssum[s], 2);
    }
    if ((lane & 3) == 0) {
        int g = lane >> 2;
        #pragma unroll
        for (int s = 0; s < 4; ++s) {
            int lrow = wr * 32 + (s >> 1) * 16 + g + (s & 1) * 8;
            sS[lrow * 2 + wc] = Ssum[s];
        }
    }
    __syncthreads();

    // ---- per-row loss: lse - pos over the 3 positives ----
    float contrib = 0.f;
    if (t < 64) {
        int myq = rb >> 11;
        float S0 = sS[t * 2] + sS[t * 2 + 1];
        #pragma unroll
        for (int qq = 0; qq < 4; ++qq) {
            if (qq == myq) continue;
            float ap = sPos[t * 4 + qq];          // = log2e * sim_pos
            contrib += logf(exp2f(ap) + S0) - ap * LN2F;
        }
    }
    #pragma unroll
    for (int off = 16; off; off >>= 1)
        contrib += __shfl_xor_sync(0xffffffffu, contrib, off);
    if (lane == 0) sRed[w] = contrib;
    __syncthreads();
    if (t == 0) g_partial[blockIdx.x] = sRed[0] + sRed[1] + sRed[2] + sRed[3];
}

// ---------------------------------------------------------------------------
// Kernel 3: final deterministic reduction.
// ---------------------------------------------------------------------------
__global__ void final_kernel(float* __restrict__ out) {
    __shared__ float sh[4];
    int t = threadIdx.x;
    float v = g_partial[t];
    #pragma unroll
    for (int off = 16; off; off >>= 1)
        v += __shfl_xor_sync(0xffffffffu, v, off);
    if ((t & 31) == 0) sh[t >> 5] = v;
    __syncthreads();
    if (t == 0) out[0] = (sh[0] + sh[1] + sh[2] + sh[3]) / KPOS;
}

// ---------------------------------------------------------------------------
extern "C" void kernel_launch(void* const* d_in, const int* in_sizes, int n_in,
                              void* d_out, int out_size) {
    const float* z = (const float*)d_in[0];
    float* out = (float*)d_out;

    cudaFuncSetAttribute(clblock_mma_kernel,
                         cudaFuncAttributeMaxDynamicSharedMemorySize, SM_TOTAL);

    normalize_kernel<<<K_TOT / 8, 256>>>(z);
    clblock_mma_kernel<<<NBLK, 128, SM_TOTAL>>>();
    final_kernel<<<1, 128>>>(out);
}

// round 5
// speedup vs baseline: 5.8455x; 1.1811x over previous
#include <cuda_runtime.h>
#include <cuda_bf16.h>
#include <cstdint>
#include <math.h>

// ---------------------------------------------------------------------------
// Problem constants
// ---------------------------------------------------------------------------
#define K_TOT 8192      // N_T * BS rows
#define D     128
#define NBLK  128       // grid of main kernel (64 rows each)
#define NCHUNK 64       // 8192 / 128 column chunks
#define KPOS  24576.0f  // N*(N-1)*BS
#define SCALE_F 1.69864368f   // sqrt(2 * log2(e));  acc = log2e * sim
#define LN2F   0.693147181f

// Smem layout (bytes)
#define SM_B0   0
#define SM_B1   32768
#define SM_A    65536          // 64 rows x 256B = 16KB
#define SM_POS  81920          // 64 x 4 floats
#define SM_SS   82944          // 64 x 4 floats
#define SM_RED  83968          // 8 floats
#define SM_TOTAL 84000

// Scratch
__device__ __align__(16) __nv_bfloat16 g_snb[K_TOT * D];
__device__ float g_partial[NBLK];

// ---------------------------------------------------------------------------
// PTX helpers
// ---------------------------------------------------------------------------
__device__ __forceinline__ float ex2f(float x) {
    float r; asm("ex2.approx.f32 %0, %1;" : "=f"(r) : "f"(x)); return r;
}

#define CP16(dst, src) \
    asm volatile("cp.async.cg.shared.global [%0], [%1], 16;\n" :: "r"(dst), "l"(src))
#define CPCOMMIT() asm volatile("cp.async.commit_group;\n")
#define CPWAIT1()  asm volatile("cp.async.wait_group 1;\n")
#define CPWAIT0()  asm volatile("cp.async.wait_group 0;\n")

#define LDSM4(R0,R1,R2,R3,ADDR) \
    asm volatile("ldmatrix.sync.aligned.m8n8.x4.shared.b16 {%0,%1,%2,%3}, [%4];\n" \
        : "=r"(R0),"=r"(R1),"=r"(R2),"=r"(R3) : "r"(ADDR))

#define MMA16816(D0,D1,D2,D3,A0,A1,A2,A3,B0,B1) \
    asm volatile("mma.sync.aligned.m16n8k16.row.col.f32.bf16.bf16.f32 " \
        "{%0,%1,%2,%3}, {%4,%5,%6,%7}, {%8,%9}, {%0,%1,%2,%3};\n" \
        : "+f"(D0),"+f"(D1),"+f"(D2),"+f"(D3) \
        : "r"(A0),"r"(A1),"r"(A2),"r"(A3),"r"(B0),"r"(B1))

// ---------------------------------------------------------------------------
// Kernel 1: row L2-normalize, pre-scale by sqrt(2*log2e), emit bf16.
// One warp per row.
// ---------------------------------------------------------------------------
__global__ void normalize_kernel(const float* __restrict__ z) {
    int gw = (blockIdx.x * blockDim.x + threadIdx.x) >> 5;
    int lane = threadIdx.x & 31;
    float4 v = ((const float4*)(z + (size_t)gw * D))[lane];
    float ss = v.x*v.x + v.y*v.y + v.z*v.z + v.w*v.w;
    #pragma unroll
    for (int off = 16; off; off >>= 1)
        ss += __shfl_xor_sync(0xffffffffu, ss, off);
    float inv = SCALE_F / fmaxf(sqrtf(ss), 1e-8f);
    __nv_bfloat162 p0 = __floats2bfloat162_rn(v.x * inv, v.y * inv);
    __nv_bfloat162 p1 = __floats2bfloat162_rn(v.z * inv, v.w * inv);
    uint2 o;
    o.x = *(unsigned int*)&p0;
    o.y = *(unsigned int*)&p1;
    *(uint2*)(g_snb + (size_t)gw * D + lane * 4) = o;
}

// ---------------------------------------------------------------------------
// B chunk loader: 128 cols x 128 k bf16 (32KB), 16B-chunk XOR swizzle.
// 2048 16B transfers over 256 threads.
// ---------------------------------------------------------------------------
__device__ __forceinline__ void load_B(uint32_t sb, int buf, int chunk, int t) {
    const char* gB = (const char*)g_snb + (size_t)chunk * 128 * 256;
    uint32_t base = sb + (buf ? SM_B1 : SM_B0);
    #pragma unroll
    for (int it = 0; it < 8; ++it) {
        int f = t + 256 * it;          // 0..2047
        int j = f >> 4, c = f & 15;
        uint32_t dst = base + j * 256 + ((c ^ (j & 7)) << 4);
        CP16(dst, gB + j * 256 + c * 16);
    }
}

// ---------------------------------------------------------------------------
// Kernel 2: HMMA simmat + exp2 accumulation + positives capture.
// 128 blocks x 256 threads (8 warps, 2 per SMSP so epilogue overlaps MMA).
// Warp grid 2x4: wr = w>>2 (32-row half), wc = w&3 (32-col group per chunk).
// A fragments register-resident for the whole kernel (64 regs).
// ---------------------------------------------------------------------------
__global__ void __launch_bounds__(256) clblock_mma_kernel() {
    extern __shared__ char smem[];
    float* sPos = (float*)(smem + SM_POS);   // [64][4]
    float* sS   = (float*)(smem + SM_SS);    // [64][4]
    float* sRed = (float*)(smem + SM_RED);   // [8]

    const int t = threadIdx.x, lane = t & 31, w = t >> 5;
    const int wr = w >> 2, wc = w & 3;
    const int rb = blockIdx.x * 64;
    const int rwb = rb + wr * 32;
    uint32_t sb = (uint32_t)__cvta_generic_to_shared(smem);

    // ---- async load A tile (64x128 bf16 = 16KB) + B chunks 0,1 ----
    {
        const char* gA = (const char*)(g_snb + (size_t)rb * D);
        #pragma unroll
        for (int it = 0; it < 4; ++it) {
            int f = t + 256 * it;      // 0..1023
            int r = f >> 4, c = f & 15;
            CP16(sb + SM_A + r * 256 + ((c ^ (r & 7)) << 4), gA + r * 256 + c * 16);
        }
        load_B(sb, 0, 0, t);
    }
    CPCOMMIT();
    load_B(sb, 1, 1, t);
    CPCOMMIT();
    CPWAIT1();              // group0 (A + chunk0) complete
    __syncthreads();

    // ---- A fragments: 2 m-tiles x 8 k-steps x 4 regs, resident ----
    uint32_t af[2][8][4];
    #pragma unroll
    for (int mt = 0; mt < 2; ++mt) {
        int row = wr * 32 + mt * 16 + (lane & 15);
        uint32_t rbase = sb + SM_A + row * 256;
        #pragma unroll
        for (int ks = 0; ks < 8; ++ks) {
            uint32_t addr = rbase + (((ks * 2 + (lane >> 4)) ^ (row & 7)) << 4);
            LDSM4(af[mt][ks][0], af[mt][ks][1], af[mt][ks][2], af[mt][ks][3], addr);
        }
    }

    float Ssum[4] = {0.f, 0.f, 0.f, 0.f};

    for (int ch = 0; ch < NCHUNK; ++ch) {
        const int cb = ch * 128;
        uint32_t Bb = sb + ((ch & 1) ? SM_B1 : SM_B0);

        float acc[2][4][4];
        #pragma unroll
        for (int mt = 0; mt < 2; ++mt)
            #pragma unroll
            for (int nt = 0; nt < 4; ++nt)
                #pragma unroll
                for (int e = 0; e < 4; ++e) acc[mt][nt][e] = 0.f;

        #pragma unroll
        for (int ks = 0; ks < 8; ++ks) {
            #pragma unroll
            for (int ntp = 0; ntp < 2; ++ntp) {
                int colr = wc * 32 + ntp * 16 + (lane & 15);
                uint32_t addr = Bb + colr * 256 +
                                (((ks * 2 + (lane >> 4)) ^ (colr & 7)) << 4);
                uint32_t b0, b1, b2, b3;
                LDSM4(b0, b1, b2, b3, addr);
                MMA16816(acc[0][2*ntp][0], acc[0][2*ntp][1], acc[0][2*ntp][2], acc[0][2*ntp][3],
                         af[0][ks][0], af[0][ks][1], af[0][ks][2], af[0][ks][3], b0, b2);
                MMA16816(acc[1][2*ntp][0], acc[1][2*ntp][1], acc[1][2*ntp][2], acc[1][2*ntp][3],
                         af[1][ks][0], af[1][ks][1], af[1][ks][2], af[1][ks][3], b0, b2);
                MMA16816(acc[0][2*ntp+1][0], acc[0][2*ntp+1][1], acc[0][2*ntp+1][2], acc[0][2*ntp+1][3],
                         af[0][ks][0], af[0][ks][1], af[0][ks][2], af[0][ks][3], b1, b3);
                MMA16816(acc[1][2*ntp+1][0], acc[1][2*ntp+1][1], acc[1][2*ntp+1][2], acc[1][2*ntp+1][3],
                         af[1][ks][0], af[1][ks][1], af[1][ks][2], af[1][ks][3], b1, b3);
            }
        }

        // Colliding columns (j == i mod 2048): chunk window must match the
        // row block, and the colliding 32-col group is exactly (rwb>>5)&3.
        bool special = (((rwb ^ cb) & 0x780) == 0) && (((rwb >> 5) & 3) == wc);
        if (!special) {
            #pragma unroll
            for (int mt = 0; mt < 2; ++mt)
                #pragma unroll
                for (int nt = 0; nt < 4; ++nt) {
                    Ssum[mt*2+0] += ex2f(acc[mt][nt][0]) + ex2f(acc[mt][nt][1]);
                    Ssum[mt*2+1] += ex2f(acc[mt][nt][2]) + ex2f(acc[mt][nt][3]);
                }
        } else {
            #pragma unroll
            for (int mt = 0; mt < 2; ++mt)
                #pragma unroll
                for (int nt = 0; nt < 4; ++nt)
                    #pragma unroll
                    for (int e = 0; e < 4; ++e) {
                        int i = rwb + mt * 16 + (lane >> 2) + ((e >> 1) << 3);
                        int j = cb + wc * 32 + nt * 8 + ((lane & 3) << 1) + (e & 1);
                        float v = acc[mt][nt][e];
                        if (((i ^ j) & 2047) == 0) {
                            if (i != j) sPos[(i - rb) * 4 + (j >> 11)] = v;
                        } else {
                            Ssum[mt*2 + (e >> 1)] += ex2f(v);
                        }
                    }
        }

        __syncthreads();                        // everyone done reading B[ch&1]
        if (ch + 2 < NCHUNK) {
            load_B(sb, ch & 1, ch + 2, t);
            CPCOMMIT();
            CPWAIT1();                          // chunk ch+1 ready
        } else if (ch + 1 < NCHUNK) {
            CPWAIT0();                          // last chunk ready
        }
        __syncthreads();
    }

    // ---- per-row partials: quad-reduce, write per (row, col-group) ----
    #pragma unroll
    for (int s = 0; s < 4; ++s) {
        Ssum[s] += __shfl_xor_sync(0xffffffffu, Ssum[s], 1);
        Ssum[s] += __shfl_xor_sync(0xffffffffu, Ssum[s], 2);
    }
    if ((lane & 3) == 0) {
        int g = lane >> 2;
        #pragma unroll
        for (int s = 0; s < 4; ++s) {
            int lrow = wr * 32 + (s >> 1) * 16 + g + (s & 1) * 8;
            sS[lrow * 4 + wc] = Ssum[s];
        }
    }
    __syncthreads();

    // ---- per-row loss: lse - pos over the 3 positives ----
    float contrib = 0.f;
    if (t < 64) {
        int myq = rb >> 11;
        float S0 = sS[t * 4] + sS[t * 4 + 1] + sS[t * 4 + 2] + sS[t * 4 + 3];
        #pragma unroll
        for (int qq = 0; qq < 4; ++qq) {
            if (qq == myq) continue;
            float ap = sPos[t * 4 + qq];          // = log2e * sim_pos
            contrib += logf(exp2f(ap) + S0) - ap * LN2F;
        }
    }
    #pragma unroll
    for (int off = 16; off; off >>= 1)
        contrib += __shfl_xor_sync(0xffffffffu, contrib, off);
    if (lane == 0) sRed[w] = contrib;
    __syncthreads();
    if (t == 0) {
        float s = 0.f;
        #pragma unroll
        for (int k = 0; k < 8; ++k) s += sRed[k];
        g_partial[blockIdx.x] = s;
    }
}

// ---------------------------------------------------------------------------
// Kernel 3: final deterministic reduction.
// ---------------------------------------------------------------------------
__global__ void final_kernel(float* __restrict__ out) {
    __shared__ float sh[4];
    int t = threadIdx.x;
    float v = g_partial[t];
    #pragma unroll
    for (int off = 16; off; off >>= 1)
        v += __shfl_xor_sync(0xffffffffu, v, off);
    if ((t & 31) == 0) sh[t >> 5] = v;
    __syncthreads();
    if (t == 0) out[0] = (sh[0] + sh[1] + sh[2] + sh[3]) / KPOS;
}

// ---------------------------------------------------------------------------
extern "C" void kernel_launch(void* const* d_in, const int* in_sizes, int n_in,
                              void* d_out, int out_size) {
    const float* z = (const float*)d_in[0];
    float* out = (float*)d_out;

    cudaFuncSetAttribute(clblock_mma_kernel,
                         cudaFuncAttributeMaxDynamicSharedMemorySize, SM_TOTAL);

    normalize_kernel<<<K_TOT / 8, 256>>>(z);
    clblock_mma_kernel<<<NBLK, 256, SM_TOTAL>>>();
    final_kernel<<<1, 128>>>(out);
}

// round 8
// speedup vs baseline: 6.2589x; 1.0707x over previous
#include <cuda_runtime.h>
#include <cuda_bf16.h>
#include <cstdint>
#include <math.h>

// ---------------------------------------------------------------------------
// Problem constants
// ---------------------------------------------------------------------------
#define K_TOT 8192      // N_T * BS rows
#define D     128
#define NBLK  128       // grid of main kernel (64 rows each)
#define NCHUNK 64       // 8192 / 128 column chunks
#define KPOS  24576.0f  // N*(N-1)*BS
#define SCALE_F 1.69864368f   // sqrt(2 * log2(e));  acc = log2e * sim
#define LN2F   0.693147181f

// Smem layout (bytes)
#define SM_B0   0
#define SM_B1   32768
#define SM_A    65536          // 64 rows x 256B = 16KB
#define SM_POS  81920          // 64 x 4 floats
#define SM_SS   82944          // 64 x 4 floats
#define SM_RED  83968          // 8 floats
#define SM_TOTAL 84000

// Scratch
__device__ __align__(16) __nv_bfloat16 g_snb[K_TOT * D];
__device__ float g_partial[NBLK];

// ---------------------------------------------------------------------------
// PTX helpers
// ---------------------------------------------------------------------------
__device__ __forceinline__ float ex2f(float x) {
    float r; asm("ex2.approx.f32 %0, %1;" : "=f"(r) : "f"(x)); return r;
}

#define CP16(dst, src) \
    asm volatile("cp.async.cg.shared.global [%0], [%1], 16;\n" :: "r"(dst), "l"(src))
#define CPCOMMIT() asm volatile("cp.async.commit_group;\n")
#define CPWAIT1()  asm volatile("cp.async.wait_group 1;\n")
#define CPWAIT0()  asm volatile("cp.async.wait_group 0;\n")

#define LDSM4(R0,R1,R2,R3,ADDR) \
    asm volatile("ldmatrix.sync.aligned.m8n8.x4.shared.b16 {%0,%1,%2,%3}, [%4];\n" \
        : "=r"(R0),"=r"(R1),"=r"(R2),"=r"(R3) : "r"(ADDR))

#define MMA16816(D0,D1,D2,D3,A0,A1,A2,A3,B0,B1) \
    asm volatile("mma.sync.aligned.m16n8k16.row.col.f32.bf16.bf16.f32 " \
        "{%0,%1,%2,%3}, {%4,%5,%6,%7}, {%8,%9}, {%0,%1,%2,%3};\n" \
        : "+f"(D0),"+f"(D1),"+f"(D2),"+f"(D3) \
        : "r"(A0),"r"(A1),"r"(A2),"r"(A3),"r"(B0),"r"(B1))

// ---------------------------------------------------------------------------
// Kernel 1: row L2-normalize, pre-scale by sqrt(2*log2e), emit bf16.
// ---------------------------------------------------------------------------
__global__ void normalize_kernel(const float* __restrict__ z) {
    int gw = (blockIdx.x * blockDim.x + threadIdx.x) >> 5;
    int lane = threadIdx.x & 31;
    float4 v = ((const float4*)(z + (size_t)gw * D))[lane];
    float ss = v.x*v.x + v.y*v.y + v.z*v.z + v.w*v.w;
    #pragma unroll
    for (int off = 16; off; off >>= 1)
        ss += __shfl_xor_sync(0xffffffffu, ss, off);
    float inv = SCALE_F / fmaxf(sqrtf(ss), 1e-8f);
    __nv_bfloat162 p0 = __floats2bfloat162_rn(v.x * inv, v.y * inv);
    __nv_bfloat162 p1 = __floats2bfloat162_rn(v.z * inv, v.w * inv);
    uint2 o;
    o.x = *(unsigned int*)&p0;
    o.y = *(unsigned int*)&p1;
    *(uint2*)(g_snb + (size_t)gw * D + lane * 4) = o;
}

// ---------------------------------------------------------------------------
// B chunk loader: 128 cols x 128 k bf16 (32KB), 16B-chunk XOR swizzle.
// ---------------------------------------------------------------------------
__device__ __forceinline__ void load_B(uint32_t sb, int buf, int chunk, int t) {
    const char* gB = (const char*)g_snb + (size_t)chunk * 128 * 256;
    uint32_t base = sb + (buf ? SM_B1 : SM_B0);
    #pragma unroll
    for (int it = 0; it < 8; ++it) {
        int f = t + 256 * it;          // 0..2047
        int j = f >> 4, c = f & 15;
        uint32_t dst = base + j * 256 + ((c ^ (j & 7)) << 4);
        CP16(dst, gB + j * 256 + c * 16);
    }
}

// ---------------------------------------------------------------------------
// MMA step for one 128-col chunk, with the ex2 epilogue of the PREVIOUS
// chunk interleaved into the k-loop (4 ex2 per k-step, same basic block, so
// MUFU issues into the tensor-pipe shadow).
// ---------------------------------------------------------------------------
template<bool DOEPI>
__device__ __forceinline__ void mma_step(
    uint32_t Bb, const uint32_t (&af)[2][8][4],
    float (&accC)[2][4][4], float (&accP)[2][4][4],
    float (&Ssum)[4], int lane, int wc)
{
    #pragma unroll
    for (int mt = 0; mt < 2; ++mt)
        #pragma unroll
        for (int nt = 0; nt < 4; ++nt)
            #pragma unroll
            for (int e = 0; e < 4; ++e) accC[mt][nt][e] = 0.f;

    #pragma unroll
    for (int ks = 0; ks < 8; ++ks) {
        #pragma unroll
        for (int ntp = 0; ntp < 2; ++ntp) {
            int colr = wc * 32 + ntp * 16 + (lane & 15);
            uint32_t addr = Bb + colr * 256 +
                            (((ks * 2 + (lane >> 4)) ^ (colr & 7)) << 4);
            uint32_t b0, b1, b2, b3;
            LDSM4(b0, b1, b2, b3, addr);
            MMA16816(accC[0][2*ntp][0], accC[0][2*ntp][1], accC[0][2*ntp][2], accC[0][2*ntp][3],
                     af[0][ks][0], af[0][ks][1], af[0][ks][2], af[0][ks][3], b0, b2);
            MMA16816(accC[1][2*ntp][0], accC[1][2*ntp][1], accC[1][2*ntp][2], accC[1][2*ntp][3],
                     af[1][ks][0], af[1][ks][1], af[1][ks][2], af[1][ks][3], b0, b2);
            MMA16816(accC[0][2*ntp+1][0], accC[0][2*ntp+1][1], accC[0][2*ntp+1][2], accC[0][2*ntp+1][3],
                     af[0][ks][0], af[0][ks][1], af[0][ks][2], af[0][ks][3], b1, b3);
            MMA16816(accC[1][2*ntp+1][0], accC[1][2*ntp+1][1], accC[1][2*ntp+1][2], accC[1][2*ntp+1][3],
                     af[1][ks][0], af[1][ks][1], af[1][ks][2], af[1][ks][3], b1, b3);
        }
        if (DOEPI) {
            #pragma unroll
            for (int q = 0; q < 4; ++q) {
                int f = ks * 4 + q;
                int mt = f >> 4, nt = (f >> 2) & 3, e = f & 3;
                Ssum[mt*2 + (e >> 1)] += ex2f(accP[mt][nt][e]);
            }
        }
    }
}

// Fixup for a colliding (special) chunk: undo the ex2 that was wrongly summed
// for j == i (mod 2048) columns and capture the positives. Exact same math as
// the branchy epilogue; runs on only ~2 of 64 chunks per warp.
__device__ __forceinline__ void fixup(
    float (&accP)[2][4][4], float* sPos, float (&Ssum)[4],
    int rb, int rwb, int cbp, int lane, int wc)
{
    #pragma unroll
    for (int mt = 0; mt < 2; ++mt)
        #pragma unroll
        for (int nt = 0; nt < 4; ++nt)
            #pragma unroll
            for (int e = 0; e < 4; ++e) {
                int i = rwb + mt * 16 + (lane >> 2) + ((e >> 1) << 3);
                int j = cbp + wc * 32 + nt * 8 + ((lane & 3) << 1) + (e & 1);
                if (((i ^ j) & 2047) == 0) {
                    float v = accP[mt][nt][e];
                    Ssum[mt*2 + (e >> 1)] -= ex2f(v);
                    if (i != j) sPos[(i - rb) * 4 + (j >> 11)] = v;
                }
            }
}

// ---------------------------------------------------------------------------
// Kernel 2: HMMA simmat + pipelined exp2 accumulation + positives capture.
// 128 blocks x 256 threads (8 warps). Warp grid 2x4: wr = w>>2 (32-row half),
// wc = w&3 (32-col group). A fragments register-resident.
// ---------------------------------------------------------------------------
__global__ void __launch_bounds__(256) clblock_mma_kernel() {
    extern __shared__ char smem[];
    float* sPos = (float*)(smem + SM_POS);   // [64][4]
    float* sS   = (float*)(smem + SM_SS);    // [64][4]
    float* sRed = (float*)(smem + SM_RED);   // [8]

    const int t = threadIdx.x, lane = t & 31, w = t >> 5;
    const int wr = w >> 2, wc = w & 3;
    const int rb = blockIdx.x * 64;
    const int rwb = rb + wr * 32;
    uint32_t sb = (uint32_t)__cvta_generic_to_shared(smem);

    // ---- async load A tile (64x128 bf16 = 16KB) + B chunks 0,1 ----
    {
        const char* gA = (const char*)(g_snb + (size_t)rb * D);
        #pragma unroll
        for (int it = 0; it < 4; ++it) {
            int f = t + 256 * it;      // 0..1023
            int r = f >> 4, c = f & 15;
            CP16(sb + SM_A + r * 256 + ((c ^ (r & 7)) << 4), gA + r * 256 + c * 16);
        }
        load_B(sb, 0, 0, t);
    }
    CPCOMMIT();
    load_B(sb, 1, 1, t);
    CPCOMMIT();
    CPWAIT1();              // group0 (A + chunk0) complete
    __syncthreads();

    // ---- A fragments: 2 m-tiles x 8 k-steps x 4 regs, resident ----
    uint32_t af[2][8][4];
    #pragma unroll
    for (int mt = 0; mt < 2; ++mt) {
        int row = wr * 32 + mt * 16 + (lane & 15);
        uint32_t rbase = sb + SM_A + row * 256;
        #pragma unroll
        for (int ks = 0; ks < 8; ++ks) {
            uint32_t addr = rbase + (((ks * 2 + (lane >> 4)) ^ (row & 7)) << 4);
            LDSM4(af[mt][ks][0], af[mt][ks][1], af[mt][ks][2], af[mt][ks][3], addr);
        }
    }

    float Ssum[4] = {0.f, 0.f, 0.f, 0.f};
    float accA[2][4][4], accB[2][4][4];

    // special(ch): this warp sees colliding columns in chunk ch
    #define SPEC(cb_) ((((rwb ^ (cb_)) & 0x780) == 0) && (((rwb >> 5) & 3) == wc))

    // Per-chunk barrier + prefetch logic (identical to R5's proven skeleton)
    #define SYNC_LOAD(ch_) do { \
        __syncthreads(); \
        if ((ch_) + 2 < NCHUNK) { \
            load_B(sb, (ch_) & 1, (ch_) + 2, t); \
            CPCOMMIT(); \
            CPWAIT1(); \
        } else if ((ch_) + 1 < NCHUNK) { \
            CPWAIT0(); \
        } \
        __syncthreads(); \
    } while (0)

    // ---- peeled ch = 0 (no previous epilogue) ----
    mma_step<false>(sb + SM_B0, af, accA, accB, Ssum, lane, wc);
    SYNC_LOAD(0);
    // ---- peeled ch = 1 (epilogue of ch 0 from accA) ----
    mma_step<true>(sb + SM_B1, af, accB, accA, Ssum, lane, wc);
    if (SPEC(0)) fixup(accA, sPos, Ssum, rb, rwb, 0, lane, wc);
    SYNC_LOAD(1);

    for (int p = 1; p < 32; ++p) {
        const int ch0 = 2 * p;
        mma_step<true>(sb + SM_B0, af, accA, accB, Ssum, lane, wc);
        if (SPEC((ch0 - 1) * 128))
            fixup(accB, sPos, Ssum, rb, rwb, (ch0 - 1) * 128, lane, wc);
        SYNC_LOAD(ch0);

        mma_step<true>(sb + SM_B1, af, accB, accA, Ssum, lane, wc);
        if (SPEC(ch0 * 128))
            fixup(accA, sPos, Ssum, rb, rwb, ch0 * 128, lane, wc);
        SYNC_LOAD(ch0 + 1);
    }

    // ---- final epilogue: chunk 63 lives in accB ----
    #pragma unroll
    for (int f = 0; f < 32; ++f) {
        int mt = f >> 4, nt = (f >> 2) & 3, e = f & 3;
        Ssum[mt*2 + (e >> 1)] += ex2f(accB[mt][nt][e]);
    }
    if (SPEC(63 * 128)) fixup(accB, sPos, Ssum, rb, rwb, 63 * 128, lane, wc);

    // ---- per-row partials: quad-reduce, write per (row, col-group) ----
    #pragma unroll
    for (int s = 0; s < 4; ++s) {
        Ssum[s] += __shfl_xor_sync(0xffffffffu, Ssum[s], 1);
        Ssum[s] += __shfl_xor_sync(0xffffffffu, Ssum[s], 2);
    }
    if ((lane & 3) == 0) {
        int g = lane >> 2;
        #pragma unroll
        for (int s = 0; s < 4; ++s) {
            int lrow = wr * 32 + (s >> 1) * 16 + g + (s & 1) * 8;
            sS[lrow * 4 + wc] = Ssum[s];
        }
    }
    __syncthreads();

    // ---- per-row loss: lse - pos over the 3 positives ----
    float contrib = 0.f;
    if (t < 64) {
        int myq = rb >> 11;
        float S0 = sS[t * 4] + sS[t * 4 + 1] + sS[t * 4 + 2] + sS[t * 4 + 3];
        #pragma unroll
        for (int qq = 0; qq < 4; ++qq) {
            if (qq == myq) continue;
            float ap = sPos[t * 4 + qq];          // = log2e * sim_pos
            contrib += logf(exp2f(ap) + S0) - ap * LN2F;
        }
    }
    #pragma unroll
    for (int off = 16; off; off >>= 1)
        contrib += __shfl_xor_sync(0xffffffffu, contrib, off);
    if (lane == 0) sRed[w] = contrib;
    __syncthreads();
    if (t == 0) {
        float s = 0.f;
        #pragma unroll
        for (int k = 0; k < 8; ++k) s += sRed[k];
        g_partial[blockIdx.x] = s;
    }
}

// ---------------------------------------------------------------------------
// Kernel 3: final deterministic reduction.
// ---------------------------------------------------------------------------
__global__ void final_kernel(float* __restrict__ out) {
    __shared__ float sh[4];
    int t = threadIdx.x;
    float v = g_partial[t];
    #pragma unroll
    for (int off = 16; off; off >>= 1)
        v += __shfl_xor_sync(0xffffffffu, v, off);
    if ((t & 31) == 0) sh[t >> 5] = v;
    __syncthreads();
    if (t == 0) out[0] = (sh[0] + sh[1] + sh[2] + sh[3]) / KPOS;
}

// ---------------------------------------------------------------------------
extern "C" void kernel_launch(void* const* d_in, const int* in_sizes, int n_in,
                              void* d_out, int out_size) {
    const float* z = (const float*)d_in[0];
    float* out = (float*)d_out;

    cudaFuncSetAttribute(clblock_mma_kernel,
                         cudaFuncAttributeMaxDynamicSharedMemorySize, SM_TOTAL);

    normalize_kernel<<<K_TOT / 8, 256>>>(z);
    clblock_mma_kernel<<<NBLK, 256, SM_TOTAL>>>();
    final_kernel<<<1, 128>>>(out);
}